// round 8
// baseline (speedup 1.0000x reference)
#include <cuda_runtime.h>
#include <cstdint>

// DenseDilatedKnnGraph: B=8, C=32, N=4096, K=9, DILATION=2 (k_all = 18)
// x: (B, C, N, 1) float32  ->  out: (2, B, N, 9), written as float32 values
//   out[0,b,n,k] = index of (2k)-th nearest neighbor of n (ascending sq-dist,
//                  ties -> lower index; matches stable top_k on -dist)
//   out[1,b,n,k] = n

#define BN   8
#define CC   32
#define NN   4096
#define KOUT 9
#define K2   18      // K * DILATION
#define QT   128     // queries per CTA (= blockDim.x)
#define CT   128     // candidate tile size
#define STRIDE 36    // floats per candidate row (32 + 4 pad); rows 16B-aligned

__global__ __launch_bounds__(QT)
void knn_dilated_kernel(const float* __restrict__ x, float* __restrict__ out) {
    __shared__ __align__(16) float stile[CT * STRIDE];
    __shared__ float ssq[CT];

    const int b = blockIdx.y;
    const int n = blockIdx.x * QT + threadIdx.x;
    const float* __restrict__ xb = x + (size_t)b * CC * NN;

    // ---- query point (coalesced across threads per channel) ----
    float q[CC];
    float sqn = 0.f;
#pragma unroll
    for (int c = 0; c < CC; ++c) {
        q[c] = xb[c * NN + n];
        sqn = fmaf(q[c], q[c], sqn);
    }

    // ---- top-18, sorted ascending, in registers ----
    float topd[K2];
    int   topi[K2];
#pragma unroll
    for (int j = 0; j < K2; ++j) { topd[j] = INFINITY; topi[j] = 0; }

    for (int tile = 0; tile < NN; tile += CT) {
        __syncthreads();
        {   // stage candidate tile (candidate-major) + norms
            const int t = threadIdx.x;
            float s = 0.f;
#pragma unroll
            for (int c = 0; c < CC; ++c) {
                float v = xb[c * NN + tile + t];
                stile[t * STRIDE + c] = v;
                s = fmaf(v, v, s);
            }
            ssq[t] = s;
        }
        __syncthreads();

        for (int t = 0; t < CT; ++t) {
            const float4* cp = (const float4*)(stile + t * STRIDE);
            float a0 = 0.f, a1 = 0.f, a2 = 0.f, a3 = 0.f;   // 4-way ILP
#pragma unroll
            for (int j = 0; j < 8; ++j) {
                float4 v = cp[j];              // LDS.128 broadcast (uniform t)
                a0 = fmaf(q[4 * j + 0], v.x, a0);
                a1 = fmaf(q[4 * j + 1], v.y, a1);
                a2 = fmaf(q[4 * j + 2], v.z, a2);
                a3 = fmaf(q[4 * j + 3], v.w, a3);
            }
            float dot = (a0 + a1) + (a2 + a3);
            // mirror reference elementwise op order: (sq - 2*inner) + sq^T
            float dist = __fadd_rn(__fsub_rn(sqn, __fmul_rn(2.0f, dot)), ssq[t]);

            if (dist < topd[K2 - 1]) {
                // predicated sorted insert (drop old max); strict '<' keeps
                // earlier (lower-m) entries ahead on ties == stable top_k
                const float cd = dist;
                const int   ci = tile + t;
                bool pprev = true;
#pragma unroll
                for (int j = K2 - 1; j > 0; --j) {
                    const bool p = cd < topd[j - 1];
                    const float nd = p ? topd[j - 1] : (pprev ? cd : topd[j]);
                    const int   ni = p ? topi[j - 1] : (pprev ? ci : topi[j]);
                    topd[j] = nd;
                    topi[j] = ni;
                    pprev = p;
                }
                if (pprev) { topd[0] = cd; topi[0] = ci; }
            }
        }
    }

    // ---- emit both halves of out (2, B, N, 9) as float32 values ----
    const size_t base0 = ((size_t)b * NN + n) * KOUT;
    const size_t base1 = (size_t)BN * NN * KOUT + base0;
    const float nf = (float)n;
#pragma unroll
    for (int k = 0; k < KOUT; ++k) {
        out[base0 + k] = (float)topi[2 * k];
        out[base1 + k] = nf;
    }
}

extern "C" void kernel_launch(void* const* d_in, const int* in_sizes, int n_in,
                              void* d_out, int out_size) {
    const float* x = (const float*)d_in[0];
    float* out = (float*)d_out;
    knn_dilated_kernel<<<dim3(NN / QT, BN), dim3(QT)>>>(x, out);
}

// round 9
// speedup vs baseline: 1.1793x; 1.1793x over previous
#include <cuda_runtime.h>
#include <cstdint>

// DenseDilatedKnnGraph: B=8, C=32, N=4096, K=9, DILATION=2
// x: (B, C, N, 1) float32  ->  out: (2, B, N, 9) float32-encoded indices
// Arithmetic is FROZEN to the R8-passing kernel (bit-identical distances,
// identical stable (dist, idx) ordering). Changes are parallelism/ILP only.

#define BN   8
#define CC   32
#define NN   4096
#define KOUT 9
#define K17  17      // only ranks 0..16 are ever emitted (even positions)
#define QT   128     // queries per CTA
#define CT   128     // candidates per tile
#define STRIDE 36    // floats per candidate row (32 + 4 pad); rows 16B-aligned
#define HALF 2048    // candidates per group

typedef unsigned long long u64;

__device__ __forceinline__ u64 fma2(u64 a, u64 b, u64 c) {
    u64 d;
    asm("fma.rn.f32x2 %0, %1, %2, %3;" : "=l"(d) : "l"(a), "l"(b), "l"(c));
    return d;
}
__device__ __forceinline__ u64 pack2(float lo, float hi) {
    u64 r;
    asm("mov.b64 %0, {%1, %2};" : "=l"(r) : "f"(lo), "f"(hi));
    return r;
}
__device__ __forceinline__ void unpack2(u64 v, float& lo, float& hi) {
    asm("mov.b64 {%0, %1}, %2;" : "=f"(lo), "=f"(hi) : "l"(v));
}

__global__ __launch_bounds__(256, 2)
void knn_dilated_kernel(const float* __restrict__ x, float* __restrict__ out) {
    // tile pool (2 groups) — reused as merge scratch after the main loop
    __shared__ __align__(16) float pool[2 * CT * STRIDE];   // 36864 B
    __shared__ float ssq[2 * CT];

    const int tid = threadIdx.x;
    const int g   = tid >> 7;          // candidate-half group 0/1
    const int t   = tid & 127;         // query lane within CTA
    const int b   = blockIdx.y;
    const int n   = blockIdx.x * QT + t;
    const float* __restrict__ xb = x + (size_t)b * CC * NN;

    // ---- query point; sqn via the SAME serial fmaf chain as R8 ----
    float sqn = 0.f;
    u64 qp[CC / 2];
#pragma unroll
    for (int i = 0; i < CC / 2; ++i) {
        float q0 = xb[(2 * i)     * NN + n];
        float q1 = xb[(2 * i + 1) * NN + n];
        sqn = fmaf(q0, q0, sqn);
        sqn = fmaf(q1, q1, sqn);
        qp[i] = pack2(q0, q1);
    }

    float topd[K17];
    int   topi[K17];
#pragma unroll
    for (int j = 0; j < K17; ++j) { topd[j] = INFINITY; topi[j] = 0; }

    float* mytile = pool + g * (CT * STRIDE);
    const int cand0 = g * HALF;

    for (int tl = 0; tl < HALF / CT; ++tl) {
        const int cbase = cand0 + tl * CT;
        __syncthreads();
        {   // stage candidate tile (candidate-major) + norms (same fmaf chain)
            float s = 0.f;
#pragma unroll
            for (int c = 0; c < CC; ++c) {
                float v = xb[c * NN + cbase + t];
                mytile[t * STRIDE + c] = v;
                s = fmaf(v, v, s);
            }
            ssq[g * CT + t] = s;
        }
        __syncthreads();

#pragma unroll 2
        for (int tt = 0; tt < CT; ++tt) {
            const ulonglong2* cp = (const ulonglong2*)(mytile + tt * STRIDE);
            u64 acc0 = 0ull, acc1 = 0ull;   // (a0,a1) and (a2,a3) lanes
#pragma unroll
            for (int j = 0; j < 8; ++j) {
                ulonglong2 v = cp[j];        // LDS.128 broadcast (uniform tt)
                acc0 = fma2(qp[2 * j],     v.x, acc0);
                acc1 = fma2(qp[2 * j + 1], v.y, acc1);
            }
            float a0, a1, a2, a3;
            unpack2(acc0, a0, a1);
            unpack2(acc1, a2, a3);
            float dot  = (a0 + a1) + (a2 + a3);          // same reduce order
            float dist = __fadd_rn(__fsub_rn(sqn, __fmul_rn(2.0f, dot)),
                                   ssq[g * CT + tt]);

            if (dist < topd[K17 - 1]) {
                // Parallel sorted insert: r[j] = max(a[j-1], min(a[j], c)),
                // index via two predicates/level (one reused). No cross-level
                // dependency. Semantics identical to R8's stable shift-insert.
                const int ci = cbase + tt;
                bool pb_hi = true;                 // c < topd[16] (guard)
#pragma unroll
                for (int j = K17 - 1; j > 0; --j) {
                    const bool pb_lo = dist < topd[j - 1];
                    topd[j] = fmaxf(topd[j - 1], fminf(topd[j], dist));
                    topi[j] = pb_lo ? topi[j - 1] : (pb_hi ? ci : topi[j]);
                    pb_hi = pb_lo;
                }
                topi[0] = pb_hi ? ci : topi[0];
                topd[0] = fminf(topd[0], dist);
            }
        }
    }

    // ---- merge the two per-group sorted lists (SMEM two-pointer) ----
    __syncthreads();                       // main-loop tile reads done
    float* sdist = pool;                   // 2*128*17 floats = 17408 B
    int*   sidx  = (int*)pool + 2 * 128 * K17;
    {
        const int base = (g * 128 + t) * K17;
#pragma unroll
        for (int j = 0; j < K17; ++j) {
            sdist[base + j] = topd[j];
            sidx[base + j]  = topi[j];
        }
    }
    __syncthreads();

    if (tid < 128) {
        const float* d0 = sdist + t * K17;
        const float* d1 = sdist + (128 + t) * K17;
        const int*   x0 = sidx  + t * K17;
        const int*   x1 = sidx  + (128 + t) * K17;
        const size_t base0 = ((size_t)b * NN + n) * KOUT;
        const size_t base1 = (size_t)BN * NN * KOUT + base0;

        int i = 0, j = 0;
#pragma unroll
        for (int r = 0; r < K17; ++r) {
            const float a = d0[i], bb = d1[j];
            // group 0 (lower indices) wins exact-distance ties == stable order
            const bool take0 = !(bb < a);
            const int idx = take0 ? x0[i] : x1[j];
            if ((r & 1) == 0) out[base0 + (r >> 1)] = (float)idx;
            i += take0 ? 1 : 0;
            j += take0 ? 0 : 1;
        }
        const float nf = (float)n;
#pragma unroll
        for (int k = 0; k < KOUT; ++k) out[base1 + k] = nf;
    }
}

extern "C" void kernel_launch(void* const* d_in, const int* in_sizes, int n_in,
                              void* d_out, int out_size) {
    const float* x = (const float*)d_in[0];
    float* out = (float*)d_out;
    knn_dilated_kernel<<<dim3(NN / QT, BN), dim3(256)>>>(x, out);
}